// round 2
// baseline (speedup 1.0000x reference)
#include <cuda_runtime.h>

// Problem constants
#define NN 50000
#define DD 64
#define HH 8
#define HD 512          // H * D
#define EE 400000
#define ET (EE + NN)    // edges + self loops
#define LN_EPS 1e-5f
#define NEG 0.2f
#define NT 16           // nodes per GEMM block tile

// ---------------- scratch (static device memory; no runtime allocation) ----
__device__ __align__(16) float g_xl[(size_t)NN * HD];   // 102.4 MB
__device__ __align__(16) float g_xr[(size_t)NN * HD];   // 102.4 MB
__device__ __align__(16) float g_xa[NN * DD];           // ping
__device__ __align__(16) float g_xb[NN * DD];           // pong
__device__ int   g_rowptr[NN + 1];
__device__ int   g_cnt[NN];
__device__ int   g_srcs[ET];              // CSR (by dst) source node ids
__device__ int   g_is64;                  // 1 if edge_index is int64, 0 if int32

// ---------------- helpers --------------------------------------------------
__device__ __forceinline__ unsigned long long pk2(float lo, float hi) {
    unsigned long long r;
    asm("mov.b64 %0, {%1, %2};" : "=l"(r) : "f"(lo), "f"(hi));
    return r;
}
__device__ __forceinline__ void upk2(unsigned long long v, float& lo, float& hi) {
    asm("mov.b64 {%0, %1}, %2;" : "=f"(lo), "=f"(hi) : "l"(v));
}
__device__ __forceinline__ void fma2(unsigned long long& d,
                                     unsigned long long a,
                                     unsigned long long b) {
    asm("fma.rn.f32x2 %0, %1, %2, %0;" : "+l"(d) : "l"(a), "l"(b));
}
__device__ __forceinline__ float lrelu(float x) {
    return x > 0.f ? x : NEG * x;
}

// fetch edge endpoint i from edge_index given dtype flag
__device__ __forceinline__ int edge_at(const void* ei, int i, int is64) {
    if (is64) return (int)((const long long*)ei)[i];
    return ((const int*)ei)[i];
}

// ---------------- dtype detection -----------------------------------------
// If edge_index is int32 (JAX default 32-bit), reading 8-byte words yields
// lo + hi*2^32 where hi is another edge value (almost surely nonzero over 16
// samples). If all 16 sampled u64 words are < NN, it is genuine int64.
__global__ void detect_kernel(const void* ei) {
    const unsigned long long* p = (const unsigned long long*)ei;
    int is64 = 1;
    for (int i = 0; i < 16; i++) {
        if (p[i] >= (unsigned long long)NN) { is64 = 0; break; }
    }
    g_is64 = is64;
}

// ---------------- CSR build ------------------------------------------------
__global__ void zero_cnt_kernel() {
    int i = blockIdx.x * blockDim.x + threadIdx.x;
    if (i < NN) g_cnt[i] = 0;
}

__global__ void count_kernel(const void* __restrict__ ei) {
    int e = blockIdx.x * blockDim.x + threadIdx.x;
    if (e >= ET) return;
    int is64 = g_is64;
    int dst = (e < EE) ? edge_at(ei, EE + e, is64) : (e - EE);
    atomicAdd(&g_cnt[dst], 1);
}

// single-block inclusive scan of g_cnt -> g_rowptr (50001 entries)
__global__ void scan_kernel() {
    __shared__ int s[1024];
    __shared__ int carry_s;
    int tid = threadIdx.x;
    if (tid == 0) { carry_s = 0; g_rowptr[0] = 0; }
    __syncthreads();
    for (int base = 0; base < NN; base += 1024) {
        int v = (base + tid < NN) ? g_cnt[base + tid] : 0;
        s[tid] = v;
        __syncthreads();
        for (int off = 1; off < 1024; off <<= 1) {
            int t = (tid >= off) ? s[tid - off] : 0;
            __syncthreads();
            s[tid] += t;
            __syncthreads();
        }
        int incl  = s[tid];
        int carry = carry_s;
        if (base + tid < NN) g_rowptr[base + tid + 1] = carry + incl;
        __syncthreads();
        if (tid == 1023) carry_s = carry + s[1023];
        __syncthreads();
    }
}

__global__ void scatter_kernel(const void* __restrict__ ei) {
    int e = blockIdx.x * blockDim.x + threadIdx.x;
    if (e >= ET) return;
    int is64 = g_is64;
    int src, dst;
    if (e < EE) { src = edge_at(ei, e, is64); dst = edge_at(ei, EE + e, is64); }
    else        { src = dst = e - EE; }
    int pos = g_rowptr[dst] + atomicAdd(&g_cnt[dst], 1);
    g_srcs[pos] = src;
}

__global__ void copyx_kernel(const float* __restrict__ x) {
    int i = blockIdx.x * blockDim.x + threadIdx.x;
    if (i < NN * DD) g_xa[i] = x[i];
}

// ---------------- GEMM: xl = x @ Wl[layer], xr = x @ Wr[layer] -------------
// grid (NN/NT, 2), block 512. Each thread owns one output column j for NT nodes.
// f32x2 lanes hold even/odd k partial sums; summed at the end.
__global__ void __launch_bounds__(512, 2)
gemm_kernel(const float* __restrict__ Wl, const float* __restrict__ Wr,
            int cursel, int layer) {
    __shared__ __align__(16) float xs[NT][DD];
    const float* xin = cursel ? g_xb : g_xa;
    int j  = threadIdx.x;                    // 0..511
    int n0 = blockIdx.x * NT;
    const float* W  = ((blockIdx.y == 0) ? Wl : Wr) + (size_t)layer * DD * HD;
    float*      out = (blockIdx.y == 0) ? g_xl : g_xr;

    for (int i = j; i < NT * DD; i += 512) {
        int n = i / DD, k = i % DD;
        xs[n][k] = xin[(n0 + n) * DD + k];   // NN % NT == 0, no guard needed
    }
    __syncthreads();

    unsigned long long acc[NT];
#pragma unroll
    for (int n = 0; n < NT; n++) acc[n] = 0ull;

#pragma unroll 4
    for (int k = 0; k < DD; k += 2) {
        unsigned long long w2 = pk2(W[k * HD + j], W[(k + 1) * HD + j]);
#pragma unroll
        for (int n = 0; n < NT; n++) {
            unsigned long long a =
                *reinterpret_cast<const unsigned long long*>(&xs[n][k]);
            fma2(acc[n], a, w2);
        }
    }
#pragma unroll
    for (int n = 0; n < NT; n++) {
        float lo, hi;
        upk2(acc[n], lo, hi);
        out[(size_t)(n0 + n) * HD + j] = lo + hi;
    }
}

// ---------------- fused edge attention + aggregation + node epilogue -------
// One block (128 threads) per destination node. Thread t owns channels
// [4t, 4t+4) of the flattened [H*D] vector (head h = t/16).
// Online softmax over incoming edges; aggregation in registers (no atomics).
__global__ void __launch_bounds__(128)
edge_node_kernel(const float* __restrict__ att, const float* __restrict__ bb,
                 const float* __restrict__ gam, const float* __restrict__ bet,
                 int cursel, float* __restrict__ out_ext, int layer) {
    int node = blockIdx.x;
    int t    = threadIdx.x;

    __shared__ __align__(16) float sm[HD];
    __shared__ float red[4];

    const float* xprev = cursel ? g_xb : g_xa;
    float* xnext = out_ext ? out_ext : (cursel ? g_xa : g_xb);

    float4 xr4 = reinterpret_cast<const float4*>(&g_xr[(size_t)node * HD])[t];
    float4 a4  = reinterpret_cast<const float4*>(att + (size_t)layer * HD)[t];

    float4 acc = make_float4(0.f, 0.f, 0.f, 0.f);
    float  den = 0.f;
    float  Mh  = -1e30f;

    int beg = g_rowptr[node], end = g_rowptr[node + 1];
    for (int e = beg; e < end; e++) {
        int s = g_srcs[e];
        float4 xl4 = reinterpret_cast<const float4*>(&g_xl[(size_t)s * HD])[t];
        float mx = lrelu(xl4.x + xr4.x);
        float my = lrelu(xl4.y + xr4.y);
        float mz = lrelu(xl4.z + xr4.z);
        float mw = lrelu(xl4.w + xr4.w);
        float p = mx * a4.x + my * a4.y + mz * a4.z + mw * a4.w;
        // reduce logit across the 16 threads of this head
        p += __shfl_xor_sync(0xffffffffu, p, 8);
        p += __shfl_xor_sync(0xffffffffu, p, 4);
        p += __shfl_xor_sync(0xffffffffu, p, 2);
        p += __shfl_xor_sync(0xffffffffu, p, 1);
        // online softmax update
        float nM   = fmaxf(Mh, p);
        float corr = __expf(Mh - nM);
        float w    = __expf(p - nM);
        den   = den * corr + w;
        acc.x = acc.x * corr + w * xl4.x;
        acc.y = acc.y * corr + w * xl4.y;
        acc.z = acc.z * corr + w * xl4.z;
        acc.w = acc.w * corr + w * xl4.w;
        Mh = nM;
    }

    float inv = 1.f / den;                 // den identical across the 16-group
    sm[4 * t + 0] = acc.x * inv;
    sm[4 * t + 1] = acc.y * inv;
    sm[4 * t + 2] = acc.z * inv;
    sm[4 * t + 3] = acc.w * inv;
    __syncthreads();

    float v = 0.f;
    if (t < DD) {
        // head mean + bias + residual
#pragma unroll
        for (int h = 0; h < HH; h++) v += sm[h * DD + t];
        v = v * (1.f / HH) + bb[layer * DD + t] + xprev[node * DD + t];
        // LayerNorm reductions (warps 0 and 1 are fully active)
        float s1 = v, s2 = v * v;
#pragma unroll
        for (int off = 16; off >= 1; off >>= 1) {
            s1 += __shfl_xor_sync(0xffffffffu, s1, off);
            s2 += __shfl_xor_sync(0xffffffffu, s2, off);
        }
        if ((t & 31) == 0) { red[(t >> 5) * 2] = s1; red[(t >> 5) * 2 + 1] = s2; }
    }
    __syncthreads();
    if (t < DD) {
        float s1 = red[0] + red[2];
        float s2 = red[1] + red[3];
        float mean = s1 * (1.f / DD);
        float var  = s2 * (1.f / DD) - mean * mean;
        float y = (v - mean) * rsqrtf(var + LN_EPS);
        y = y * gam[layer * DD + t] + bet[layer * DD + t];
        y = fmaxf(y, 0.f);
        xnext[node * DD + t] = y;
    }
}

// ---------------- launch ---------------------------------------------------
extern "C" void kernel_launch(void* const* d_in, const int* in_sizes, int n_in,
                              void* d_out, int out_size) {
    const float* x   = (const float*)d_in[0];
    const float* Wl  = (const float*)d_in[1];
    const float* Wr  = (const float*)d_in[2];
    const float* att = (const float*)d_in[3];
    const float* b   = (const float*)d_in[4];
    const float* gam = (const float*)d_in[5];
    const float* bet = (const float*)d_in[6];
    const void*  ei  = (const void*)d_in[7];   // int32 or int64, detected on-device
    float* out = (float*)d_out;

    // CSR by destination (recomputed every call: deterministic, cheap)
    detect_kernel<<<1, 1>>>(ei);
    zero_cnt_kernel<<<(NN + 255) / 256, 256>>>();
    count_kernel<<<(ET + 255) / 256, 256>>>(ei);
    scan_kernel<<<1, 1024>>>();
    zero_cnt_kernel<<<(NN + 255) / 256, 256>>>();
    scatter_kernel<<<(ET + 255) / 256, 256>>>(ei);

    copyx_kernel<<<(NN * DD + 255) / 256, 256>>>(x);

    for (int l = 0; l < 3; l++) {
        int cursel = l & 1;                    // 0: read g_xa, 1: read g_xb
        dim3 ggrid(NN / NT, 2);
        gemm_kernel<<<ggrid, 512>>>(Wl, Wr, cursel, l);
        float* oext = (l == 2) ? out : nullptr;
        edge_node_kernel<<<NN, 128>>>(att, b, gam, bet, cursel, oext, l);
    }
}

// round 4
// speedup vs baseline: 1.9523x; 1.9523x over previous
#include <cuda_runtime.h>

// Problem constants
#define NN 50000
#define DD 64
#define HH 8
#define HD 512          // H * D
#define EE 400000
#define ET (EE + NN)    // edges + self loops
#define LN_EPS 1e-5f
#define NEG 0.2f
#define GNT 16          // nodes per GEMM block tile
#define XSP 18          // padded smem row stride (floats); 72B keeps 8B align

// ---------------- scratch (static device memory) ---------------------------
__device__ __align__(16) float g_xl[(size_t)NN * HD];   // 102.4 MB
__device__ __align__(16) float g_xr[(size_t)NN * HD];   // 102.4 MB
__device__ __align__(16) float g_xa[NN * DD];
__device__ __align__(16) float g_xb[NN * DD];
__device__ int   g_rowptr[NN + 1];
__device__ int   g_cnt[NN];
__device__ int   g_srcs[ET];
__device__ int   g_is64;

// ---------------- helpers --------------------------------------------------
__device__ __forceinline__ unsigned long long pk2(float lo, float hi) {
    unsigned long long r;
    asm("mov.b64 %0, {%1, %2};" : "=l"(r) : "f"(lo), "f"(hi));
    return r;
}
__device__ __forceinline__ void upk2(unsigned long long v, float& lo, float& hi) {
    asm("mov.b64 {%0, %1}, %2;" : "=f"(lo), "=f"(hi) : "l"(v));
}
__device__ __forceinline__ void fma2(unsigned long long& d,
                                     unsigned long long a,
                                     unsigned long long b) {
    asm("fma.rn.f32x2 %0, %1, %2, %0;" : "+l"(d) : "l"(a), "l"(b));
}
__device__ __forceinline__ float lrelu(float x) {
    return x > 0.f ? x : NEG * x;
}
__device__ __forceinline__ int edge_at(const void* ei, int i, int is64) {
    if (is64) return (int)((const long long*)ei)[i];
    return ((const int*)ei)[i];
}

// ---------------- dtype detection ------------------------------------------
__global__ void detect_kernel(const void* ei) {
    const unsigned long long* p = (const unsigned long long*)ei;
    int is64 = 1;
    for (int i = 0; i < 16; i++)
        if (p[i] >= (unsigned long long)NN) { is64 = 0; break; }
    g_is64 = is64;
}

// ---------------- CSR build ------------------------------------------------
__global__ void zero_cnt_kernel() {
    int i = blockIdx.x * blockDim.x + threadIdx.x;
    if (i < NN) g_cnt[i] = 0;
}

__global__ void count_kernel(const void* __restrict__ ei) {
    int e = blockIdx.x * blockDim.x + threadIdx.x;
    if (e >= ET) return;
    int is64 = g_is64;
    int dst = (e < EE) ? edge_at(ei, EE + e, is64) : (e - EE);
    atomicAdd(&g_cnt[dst], 1);
}

// scan: 1024 threads, each owns a chunk of 49; local sum -> block scan -> fill
__global__ void scan_kernel() {
    __shared__ int wsum[32];
    const int CH = (NN + 1023) / 1024;   // 49
    int tid  = threadIdx.x;
    int lane = tid & 31, warp = tid >> 5;
    int base = tid * CH;
    int lim  = min(base + CH, NN);

    int s = 0;
    for (int i = base; i < lim; i++) s += g_cnt[i];

    // inclusive warp scan
    int v = s;
#pragma unroll
    for (int off = 1; off < 32; off <<= 1) {
        int t = __shfl_up_sync(0xffffffffu, v, off);
        if (lane >= off) v += t;
    }
    if (lane == 31) wsum[warp] = v;
    __syncthreads();
    if (warp == 0) {
        int w = (lane < 32) ? wsum[lane] : 0;
#pragma unroll
        for (int off = 1; off < 32; off <<= 1) {
            int t = __shfl_up_sync(0xffffffffu, w, off);
            if (lane >= off) w += t;
        }
        wsum[lane] = w;
    }
    __syncthreads();
    int excl = v - s + (warp ? wsum[warp - 1] : 0);   // exclusive prefix of chunk

    if (tid == 0) g_rowptr[0] = 0;
    int run = excl;
    for (int i = base; i < lim; i++) {
        run += g_cnt[i];
        g_rowptr[i + 1] = run;
    }
}

__global__ void scatter_kernel(const void* __restrict__ ei) {
    int e = blockIdx.x * blockDim.x + threadIdx.x;
    if (e >= ET) return;
    int is64 = g_is64;
    int src, dst;
    if (e < EE) { src = edge_at(ei, e, is64); dst = edge_at(ei, EE + e, is64); }
    else        { src = dst = e - EE; }
    int pos = g_rowptr[dst] + atomicAdd(&g_cnt[dst], 1);
    g_srcs[pos] = src;
}

// ---------------- GEMM: out = xin @ W  (both Wl and Wr via grid.y) ---------
// Block 256 threads, GNT=16 nodes. Node-pairs packed into f32x2 lanes:
// acc(pair p, col j) lanes = (node 2p, node 2p+1). W value broadcast to both.
// Each thread owns columns j and j+256.
__global__ void __launch_bounds__(256)
gemm_kernel(const float* __restrict__ xin,
            const float* __restrict__ Wl, const float* __restrict__ Wr,
            int layer) {
    __shared__ __align__(16) float xs[DD][XSP];   // transposed [k][n], padded
    int tid = threadIdx.x;
    int n0  = blockIdx.x * GNT;
    const float* W  = ((blockIdx.y == 0) ? Wl : Wr) + (size_t)layer * DD * HD;
    float*      out = (blockIdx.y == 0) ? g_xl : g_xr;

    for (int i = tid; i < GNT * DD; i += 256) {
        int n = i >> 6, k = i & 63;
        xs[k][n] = xin[(n0 + n) * DD + k];
    }
    __syncthreads();

    int j0 = tid, j1 = tid + 256;
    unsigned long long acc0[GNT / 2], acc1[GNT / 2];
#pragma unroll
    for (int p = 0; p < GNT / 2; p++) { acc0[p] = 0ull; acc1[p] = 0ull; }

#pragma unroll 8
    for (int k = 0; k < DD; k++) {
        float w0 = __ldg(&W[k * HD + j0]);
        float w1 = __ldg(&W[k * HD + j1]);
        unsigned long long w02 = pk2(w0, w0);
        unsigned long long w12 = pk2(w1, w1);
#pragma unroll
        for (int p = 0; p < GNT / 2; p++) {
            unsigned long long a =
                *reinterpret_cast<const unsigned long long*>(&xs[k][2 * p]);
            fma2(acc0[p], a, w02);
            fma2(acc1[p], a, w12);
        }
    }
#pragma unroll
    for (int p = 0; p < GNT / 2; p++) {
        float a, b;
        upk2(acc0[p], a, b);
        out[(size_t)(n0 + 2 * p) * HD + j0]     = a;
        out[(size_t)(n0 + 2 * p + 1) * HD + j0] = b;
        upk2(acc1[p], a, b);
        out[(size_t)(n0 + 2 * p) * HD + j1]     = a;
        out[(size_t)(n0 + 2 * p + 1) * HD + j1] = b;
    }
}

// ---------------- fused edge attention + aggregation + node epilogue -------
// One block (128 threads) per dst node; thread t owns channels [4t,4t+4).
// Online softmax; next edge's gather prefetched to overlap the shfl/exp chain.
__global__ void __launch_bounds__(128)
edge_node_kernel(const float* __restrict__ att, const float* __restrict__ bb,
                 const float* __restrict__ gam, const float* __restrict__ bet,
                 const float* __restrict__ xprev, float* __restrict__ xnext,
                 int layer) {
    int node = blockIdx.x;
    int t    = threadIdx.x;

    __shared__ __align__(16) float sm[HD];
    __shared__ float red[4];

    float4 xr4 = reinterpret_cast<const float4*>(&g_xr[(size_t)node * HD])[t];
    float4 a4  = reinterpret_cast<const float4*>(att + (size_t)layer * HD)[t];

    float4 acc = make_float4(0.f, 0.f, 0.f, 0.f);
    float  den = 0.f;
    float  Mh  = -1e30f;

    int beg = g_rowptr[node], end = g_rowptr[node + 1];

    float4 cur;
    if (beg < end) {
        int s0 = __ldg(&g_srcs[beg]);
        cur = reinterpret_cast<const float4*>(&g_xl[(size_t)s0 * HD])[t];
    }
    for (int e = beg; e < end; e++) {
        float4 xl4 = cur;
        if (e + 1 < end) {
            int sn = __ldg(&g_srcs[e + 1]);
            cur = reinterpret_cast<const float4*>(&g_xl[(size_t)sn * HD])[t];
        }
        float mx = lrelu(xl4.x + xr4.x);
        float my = lrelu(xl4.y + xr4.y);
        float mz = lrelu(xl4.z + xr4.z);
        float mw = lrelu(xl4.w + xr4.w);
        float p = mx * a4.x + my * a4.y + mz * a4.z + mw * a4.w;
        p += __shfl_xor_sync(0xffffffffu, p, 8);
        p += __shfl_xor_sync(0xffffffffu, p, 4);
        p += __shfl_xor_sync(0xffffffffu, p, 2);
        p += __shfl_xor_sync(0xffffffffu, p, 1);
        float nM   = fmaxf(Mh, p);
        float corr = __expf(Mh - nM);
        float w    = __expf(p - nM);
        den   = den * corr + w;
        acc.x = acc.x * corr + w * xl4.x;
        acc.y = acc.y * corr + w * xl4.y;
        acc.z = acc.z * corr + w * xl4.z;
        acc.w = acc.w * corr + w * xl4.w;
        Mh = nM;
    }

    float inv = 1.f / den;
    sm[4 * t + 0] = acc.x * inv;
    sm[4 * t + 1] = acc.y * inv;
    sm[4 * t + 2] = acc.z * inv;
    sm[4 * t + 3] = acc.w * inv;
    __syncthreads();

    float v = 0.f;
    if (t < DD) {
#pragma unroll
        for (int h = 0; h < HH; h++) v += sm[h * DD + t];
        v = v * (1.f / HH) + bb[layer * DD + t] + xprev[node * DD + t];
        float s1 = v, s2 = v * v;
#pragma unroll
        for (int off = 16; off >= 1; off >>= 1) {
            s1 += __shfl_xor_sync(0xffffffffu, s1, off);
            s2 += __shfl_xor_sync(0xffffffffu, s2, off);
        }
        if ((t & 31) == 0) { red[(t >> 5) * 2] = s1; red[(t >> 5) * 2 + 1] = s2; }
    }
    __syncthreads();
    if (t < DD) {
        float s1 = red[0] + red[2];
        float s2 = red[1] + red[3];
        float mean = s1 * (1.f / DD);
        float var  = s2 * (1.f / DD) - mean * mean;
        float y = (v - mean) * rsqrtf(var + LN_EPS);
        y = y * gam[layer * DD + t] + bet[layer * DD + t];
        y = fmaxf(y, 0.f);
        xnext[node * DD + t] = y;
    }
}

// ---------------- launch ---------------------------------------------------
extern "C" void kernel_launch(void* const* d_in, const int* in_sizes, int n_in,
                              void* d_out, int out_size) {
    const float* x   = (const float*)d_in[0];
    const float* Wl  = (const float*)d_in[1];
    const float* Wr  = (const float*)d_in[2];
    const float* att = (const float*)d_in[3];
    const float* b   = (const float*)d_in[4];
    const float* gam = (const float*)d_in[5];
    const float* bet = (const float*)d_in[6];
    const void*  ei  = (const void*)d_in[7];
    float* out = (float*)d_out;

    detect_kernel<<<1, 1>>>(ei);
    zero_cnt_kernel<<<(NN + 255) / 256, 256>>>();
    count_kernel<<<(ET + 255) / 256, 256>>>(ei);
    scan_kernel<<<1, 1024>>>();
    zero_cnt_kernel<<<(NN + 255) / 256, 256>>>();
    scatter_kernel<<<(ET + 255) / 256, 256>>>(ei);

    // layer I/O chaining: x -> g_xb -> g_xa -> out
    const float* xin[3]  = { x, g_xb, g_xa };
    float*       xout[3] = { g_xb, g_xa, out };

    for (int l = 0; l < 3; l++) {
        dim3 ggrid(NN / GNT, 2);
        gemm_kernel<<<ggrid, 256>>>(xin[l], Wl, Wr, l);
        edge_node_kernel<<<NN, 128>>>(att, b, gam, bet, xin[l], xout[l], l);
    }
}

// round 6
// speedup vs baseline: 2.0801x; 1.0654x over previous
#include <cuda_runtime.h>

// Problem constants
#define NN 50000
#define DD 64
#define HH 8
#define HD 512          // H * D
#define EE 400000
#define ET (EE + NN)    // edges + self loops
#define LN_EPS 1e-5f
#define NEG 0.2f
#define GNT 16          // nodes per GEMM block tile
#define XSP 18          // padded smem row stride (floats)
#define NSB 98          // scan blocks (98*512 >= 50000)

// ---------------- scratch (static device memory) ---------------------------
__device__ __align__(16) float g_xl[(size_t)NN * HD];   // 102.4 MB
__device__ __align__(16) float g_xr[(size_t)NN * HD];   // 102.4 MB
__device__ __align__(16) float g_xa[NN * DD];
__device__ __align__(16) float g_xb[NN * DD];
__device__ int g_rowptr[NN + 1];
__device__ int g_cnt[NN];
__device__ int g_srcs[ET];
__device__ int g_is64;
__device__ int g_bsum[NSB];
__device__ int g_boff[NSB];

// ---------------- helpers --------------------------------------------------
__device__ __forceinline__ unsigned long long pk2(float lo, float hi) {
    unsigned long long r;
    asm("mov.b64 %0, {%1, %2};" : "=l"(r) : "f"(lo), "f"(hi));
    return r;
}
__device__ __forceinline__ void upk2(unsigned long long v, float& lo, float& hi) {
    asm("mov.b64 {%0, %1}, %2;" : "=f"(lo), "=f"(hi) : "l"(v));
}
__device__ __forceinline__ void fma2(unsigned long long& d,
                                     unsigned long long a,
                                     unsigned long long b) {
    asm("fma.rn.f32x2 %0, %1, %2, %0;" : "+l"(d) : "l"(a), "l"(b));
}
__device__ __forceinline__ float lrelu(float x) { return x > 0.f ? x : NEG * x; }
__device__ __forceinline__ int edge_at(const void* ei, int i, int is64) {
    if (is64) return (int)((const long long*)ei)[i];
    return ((const int*)ei)[i];
}

// ---------------- CSR build ------------------------------------------------
// zero counts; block 0 thread 0 also detects edge dtype
__global__ void zero_detect_kernel(const void* ei) {
    int i = blockIdx.x * blockDim.x + threadIdx.x;
    if (i < NN) g_cnt[i] = 0;
    if (i == 0) {
        const unsigned long long* p = (const unsigned long long*)ei;
        int is64 = 1;
        for (int k = 0; k < 16; k++)
            if (p[k] >= (unsigned long long)NN) { is64 = 0; break; }
        g_is64 = is64;
    }
}

__global__ void zero_cnt_kernel() {
    int i = blockIdx.x * blockDim.x + threadIdx.x;
    if (i < NN) g_cnt[i] = 0;
}

__global__ void count_kernel(const void* __restrict__ ei) {
    int e = blockIdx.x * blockDim.x + threadIdx.x;
    if (e >= ET) return;
    int is64 = g_is64;
    int dst = (e < EE) ? edge_at(ei, EE + e, is64) : (e - EE);
    atomicAdd(&g_cnt[dst], 1);
}

// multi-block scan: per-block inclusive scan + block totals
__global__ void scan1_kernel() {
    __shared__ int ws[16];
    int tid = threadIdx.x, lane = tid & 31, w = tid >> 5;
    int i = blockIdx.x * 512 + tid;
    int v = (i < NN) ? g_cnt[i] : 0;
    int x = v;
#pragma unroll
    for (int off = 1; off < 32; off <<= 1) {
        int t = __shfl_up_sync(0xffffffffu, x, off);
        if (lane >= off) x += t;
    }
    if (lane == 31) ws[w] = x;
    __syncthreads();
    if (w == 0) {
        int y = (lane < 16) ? ws[lane] : 0;
#pragma unroll
        for (int off = 1; off < 16; off <<= 1) {
            int t = __shfl_up_sync(0xffffffffu, y, off);
            if (lane >= off) y += t;
        }
        if (lane < 16) ws[lane] = y;
    }
    __syncthreads();
    int incl = x + (w ? ws[w - 1] : 0);
    if (i < NN) g_rowptr[i + 1] = incl;
    if (tid == 511) g_bsum[blockIdx.x] = incl;
}

__global__ void scan2_kernel() {   // serial exclusive scan of block sums
    int run = 0;
    for (int b = 0; b < NSB; b++) { g_boff[b] = run; run += g_bsum[b]; }
    g_rowptr[0] = 0;
}

__global__ void scan3_kernel() {
    int i = blockIdx.x * 512 + threadIdx.x;
    if (i < NN) g_rowptr[i + 1] += g_boff[blockIdx.x];
}

__global__ void scatter_kernel(const void* __restrict__ ei) {
    int e = blockIdx.x * blockDim.x + threadIdx.x;
    if (e >= ET) return;
    int is64 = g_is64;
    int src, dst;
    if (e < EE) { src = edge_at(ei, e, is64); dst = edge_at(ei, EE + e, is64); }
    else        { src = dst = e - EE; }
    int pos = g_rowptr[dst] + atomicAdd(&g_cnt[dst], 1);
    g_srcs[pos] = src;
}

// ---------------- GEMM: out = xin @ W  (both Wl and Wr via grid.y) ---------
// (unchanged from the 1053us pass)
__global__ void __launch_bounds__(256)
gemm_kernel(const float* __restrict__ xin,
            const float* __restrict__ Wl, const float* __restrict__ Wr,
            int layer) {
    __shared__ __align__(16) float xs[DD][XSP];
    int tid = threadIdx.x;
    int n0  = blockIdx.x * GNT;
    const float* W  = ((blockIdx.y == 0) ? Wl : Wr) + (size_t)layer * DD * HD;
    float*      out = (blockIdx.y == 0) ? g_xl : g_xr;

    for (int i = tid; i < GNT * DD; i += 256) {
        int n = i >> 6, k = i & 63;
        xs[k][n] = xin[(n0 + n) * DD + k];
    }
    __syncthreads();

    int j0 = tid, j1 = tid + 256;
    unsigned long long acc0[GNT / 2], acc1[GNT / 2];
#pragma unroll
    for (int p = 0; p < GNT / 2; p++) { acc0[p] = 0ull; acc1[p] = 0ull; }

#pragma unroll 8
    for (int k = 0; k < DD; k++) {
        float w0 = __ldg(&W[k * HD + j0]);
        float w1 = __ldg(&W[k * HD + j1]);
        unsigned long long w02 = pk2(w0, w0);
        unsigned long long w12 = pk2(w1, w1);
#pragma unroll
        for (int p = 0; p < GNT / 2; p++) {
            unsigned long long a =
                *reinterpret_cast<const unsigned long long*>(&xs[k][2 * p]);
            fma2(acc0[p], a, w02);
            fma2(acc1[p], a, w12);
        }
    }
#pragma unroll
    for (int p = 0; p < GNT / 2; p++) {
        float a, b;
        upk2(acc0[p], a, b);
        out[(size_t)(n0 + 2 * p) * HD + j0]     = a;
        out[(size_t)(n0 + 2 * p + 1) * HD + j0] = b;
        upk2(acc1[p], a, b);
        out[(size_t)(n0 + 2 * p) * HD + j1]     = a;
        out[(size_t)(n0 + 2 * p + 1) * HD + j1] = b;
    }
}

// ---------------- fused edge attention + aggregation + node epilogue -------
// One block (128 threads) per dst node; thread t owns channels [4t,4t+4).
// TWO interleaved online-softmax states (even/odd edges) merged exactly at
// the end -> 2x ILP on the serial shfl/exp chain; 2 gathers in flight.
__global__ void __launch_bounds__(128)
edge_node_kernel(const float* __restrict__ att, const float* __restrict__ bb,
                 const float* __restrict__ gam, const float* __restrict__ bet,
                 const float* __restrict__ xprev, float* __restrict__ xnext,
                 int layer) {
    int node = blockIdx.x;
    int t    = threadIdx.x;

    __shared__ __align__(16) float sm[HD];
    __shared__ float red[4];

    float4 xr4 = reinterpret_cast<const float4*>(&g_xr[(size_t)node * HD])[t];
    float4 a4  = reinterpret_cast<const float4*>(att + (size_t)layer * HD)[t];

    float4 accA = make_float4(0.f, 0.f, 0.f, 0.f);
    float4 accB = make_float4(0.f, 0.f, 0.f, 0.f);
    float denA = 0.f, denB = 0.f;
    float MA = -1e30f, MB = -1e30f;

    int beg = g_rowptr[node], end = g_rowptr[node + 1];
    int e = beg;

    for (; e + 1 < end; e += 2) {
        int s0 = __ldg(&g_srcs[e]);
        int s1 = __ldg(&g_srcs[e + 1]);
        float4 va = reinterpret_cast<const float4*>(&g_xl[(size_t)s0 * HD])[t];
        float4 vb = reinterpret_cast<const float4*>(&g_xl[(size_t)s1 * HD])[t];

        float pA = lrelu(va.x + xr4.x) * a4.x + lrelu(va.y + xr4.y) * a4.y +
                   lrelu(va.z + xr4.z) * a4.z + lrelu(va.w + xr4.w) * a4.w;
        float pB = lrelu(vb.x + xr4.x) * a4.x + lrelu(vb.y + xr4.y) * a4.y +
                   lrelu(vb.z + xr4.z) * a4.z + lrelu(vb.w + xr4.w) * a4.w;
#pragma unroll
        for (int off = 8; off >= 1; off >>= 1) {
            pA += __shfl_xor_sync(0xffffffffu, pA, off);
            pB += __shfl_xor_sync(0xffffffffu, pB, off);
        }
        float nMA = fmaxf(MA, pA);
        float nMB = fmaxf(MB, pB);
        float cA = __expf(MA - nMA), wA = __expf(pA - nMA);
        float cB = __expf(MB - nMB), wB = __expf(pB - nMB);
        denA = denA * cA + wA;
        denB = denB * cB + wB;
        accA.x = accA.x * cA + wA * va.x;  accB.x = accB.x * cB + wB * vb.x;
        accA.y = accA.y * cA + wA * va.y;  accB.y = accB.y * cB + wB * vb.y;
        accA.z = accA.z * cA + wA * va.z;  accB.z = accB.z * cB + wB * vb.z;
        accA.w = accA.w * cA + wA * va.w;  accB.w = accB.w * cB + wB * vb.w;
        MA = nMA; MB = nMB;
    }
    if (e < end) {   // tail edge -> state A
        int s0 = __ldg(&g_srcs[e]);
        float4 va = reinterpret_cast<const float4*>(&g_xl[(size_t)s0 * HD])[t];
        float pA = lrelu(va.x + xr4.x) * a4.x + lrelu(va.y + xr4.y) * a4.y +
                   lrelu(va.z + xr4.z) * a4.z + lrelu(va.w + xr4.w) * a4.w;
#pragma unroll
        for (int off = 8; off >= 1; off >>= 1)
            pA += __shfl_xor_sync(0xffffffffu, pA, off);
        float nMA = fmaxf(MA, pA);
        float cA = __expf(MA - nMA), wA = __expf(pA - nMA);
        denA = denA * cA + wA;
        accA.x = accA.x * cA + wA * va.x;
        accA.y = accA.y * cA + wA * va.y;
        accA.z = accA.z * cA + wA * va.z;
        accA.w = accA.w * cA + wA * va.w;
        MA = nMA;
    }

    // exact merge of the two online states
    float M  = fmaxf(MA, MB);
    float cA = __expf(MA - M), cB = __expf(MB - M);
    float den = denA * cA + denB * cB;
    float4 acc;
    acc.x = accA.x * cA + accB.x * cB;
    acc.y = accA.y * cA + accB.y * cB;
    acc.z = accA.z * cA + accB.z * cB;
    acc.w = accA.w * cA + accB.w * cB;

    float inv = 1.f / den;
    sm[4 * t + 0] = acc.x * inv;
    sm[4 * t + 1] = acc.y * inv;
    sm[4 * t + 2] = acc.z * inv;
    sm[4 * t + 3] = acc.w * inv;
    __syncthreads();

    float v = 0.f;
    if (t < DD) {
#pragma unroll
        for (int h = 0; h < HH; h++) v += sm[h * DD + t];
        v = v * (1.f / HH) + bb[layer * DD + t] + xprev[node * DD + t];
        float s1 = v, s2 = v * v;
#pragma unroll
        for (int off = 16; off >= 1; off >>= 1) {
            s1 += __shfl_xor_sync(0xffffffffu, s1, off);
            s2 += __shfl_xor_sync(0xffffffffu, s2, off);
        }
        if ((t & 31) == 0) { red[(t >> 5) * 2] = s1; red[(t >> 5) * 2 + 1] = s2; }
    }
    __syncthreads();
    if (t < DD) {
        float s1 = red[0] + red[2];
        float s2 = red[1] + red[3];
        float mean = s1 * (1.f / DD);
        float var  = s2 * (1.f / DD) - mean * mean;
        float y = (v - mean) * rsqrtf(var + LN_EPS);
        y = y * gam[layer * DD + t] + bet[layer * DD + t];
        y = fmaxf(y, 0.f);
        xnext[node * DD + t] = y;
    }
}

// ---------------- launch ---------------------------------------------------
extern "C" void kernel_launch(void* const* d_in, const int* in_sizes, int n_in,
                              void* d_out, int out_size) {
    const float* x   = (const float*)d_in[0];
    const float* Wl  = (const float*)d_in[1];
    const float* Wr  = (const float*)d_in[2];
    const float* att = (const float*)d_in[3];
    const float* b   = (const float*)d_in[4];
    const float* gam = (const float*)d_in[5];
    const float* bet = (const float*)d_in[6];
    const void*  ei  = (const void*)d_in[7];
    float* out = (float*)d_out;

    zero_detect_kernel<<<(NN + 255) / 256, 256>>>(ei);
    count_kernel<<<(ET + 255) / 256, 256>>>(ei);
    scan1_kernel<<<NSB, 512>>>();
    scan2_kernel<<<1, 1>>>();
    scan3_kernel<<<NSB, 512>>>();
    zero_cnt_kernel<<<(NN + 255) / 256, 256>>>();
    scatter_kernel<<<(ET + 255) / 256, 256>>>(ei);

    const float* xin[3]  = { x, g_xb, g_xa };
    float*       xout[3] = { g_xb, g_xa, out };

    for (int l = 0; l < 3; l++) {
        dim3 ggrid(NN / GNT, 2);
        gemm_kernel<<<ggrid, 256>>>(xin[l], Wl, Wr, l);
        edge_node_kernel<<<NN, 128>>>(att, b, gam, bet, xin[l], xout[l], l);
    }
}